// round 10
// baseline (speedup 1.0000x reference)
#include <cuda_runtime.h>

#define LMAX   10
#define NIDX   121     // 11*11 coeff block per batch element
#define NCOLS  381
#define NPAIRS 66
#define NW     8       // warps (batch elements) per CTA

__device__ __forceinline__ int iclamp(int x, int hi) { return x < hi ? x : hi; }

// ---------------------------------------------------------------------------
// One warp = one (batch element, pair). Lane owns columns k = lane + 32*i.
//   tp[j]         = f1[j1] * f2[j2]              (complex, per-lane redundant)
//   transformed_k = sum_j tp[j] * cg[j*d + k]    (cg real)
//   out[l block]  = Re( sum_k transformed_k * conj(F3_k) )   [float32 output]
// No block-wide sync, no device scratch, all global accesses clamped/guarded.
// ---------------------------------------------------------------------------
__global__ void __launch_bounds__(NW * 32)
so3_kernel(const float* __restrict__ cre, const float* __restrict__ cim,
           const float* __restrict__ cg, float* __restrict__ outf,
           int B, int coeff_elems, int cg_elems, int out_elems)
{
    // Derive this pair's parameters from blockIdx.y (cheap integer loop).
    const int p = blockIdx.y;
    int l1 = 0, l2 = 0, cg_off = 0, col_base = 0;
    {
        int off = 0, col = 0, cnt = 0;
        for (int a = 0; a <= LMAX; a++) {
            for (int c = a; c <= LMAX; c++) {
                int dd  = (2 * a + 1) * (2 * c + 1);
                int lmn = c - a;
                int lmx2 = (a + c < LMAX) ? (a + c) : LMAX;
                if (cnt == p) { l1 = a; l2 = c; cg_off = off; col_base = col; }
                off += dd * dd;
                col += lmx2 - lmn + 1;
                cnt++;
            }
        }
    }
    const int d1   = 2 * l1 + 1;
    const int d2   = 2 * l2 + 1;
    const int d    = d1 * d2;
    const int lmin = l2 - l1;
    const int lmx  = (l1 + l2 < LMAX) ? (l1 + l2) : LMAX;
    const int K    = (lmx + 1) * (lmx + 1) - lmin * lmin;   // used columns
    const int nl   = lmx - lmin + 1;

    const int warp = (int)(threadIdx.x >> 5);
    const int lane = (int)(threadIdx.x & 31);
    const int b    = blockIdx.x * NW + warp;
    if (b >= B) return;                       // warp-uniform exit, no block sync

    __shared__ float2 sh_f[NW][42];           // f1 (d1) then f2 (d2)
    __shared__ float  sh_p[NW][128];          // epilogue real products

    // Stage f1 | f2 for this batch element (conj mirror built inline).
    for (int t = lane; t < d1 + d2; t += 32) {
        int l = (t < d1) ? l1 : l2;
        int m = (t < d1) ? (t - l1) : (t - d1 - l2);
        int a = (m < 0) ? -m : m;
        int src = iclamp(b * NIDX + l * (LMAX + 1) + a, coeff_elems - 1);
        float re = cre[src], im = cim[src];
        if (m < 0) { float s = (a & 1) ? -1.f : 1.f; re *= s; im *= -s; }
        sh_f[warp][t] = make_float2(re, im);
    }
    __syncwarp();

    float ax[4] = {0.f, 0.f, 0.f, 0.f};
    float ay[4] = {0.f, 0.f, 0.f, 0.f};

    int j = 0;
    for (int j1 = 0; j1 < d1; j1++) {
        const float2 f1 = sh_f[warp][j1];
        for (int j2 = 0; j2 < d2; j2++, j++) {
            const float2 f2 = sh_f[warp][d1 + j2];
            const float tx = f1.x * f2.x - f1.y * f2.y;
            const float ty = f1.x * f2.y + f1.y * f2.x;
            const int rb = cg_off + j * d;
#pragma unroll
            for (int i = 0; i < 4; i++) {
                int k = lane + 32 * i;
                if (k < K) {                  // K <= d, so also within the row
                    float c = cg[iclamp(rb + k, cg_elems - 1)];
                    ax[i] += tx * c;
                    ay[i] += ty * c;
                }
            }
        }
    }

    // Epilogue: Re( transformed_k * conj(F3_k) ) into per-warp shared.
#pragma unroll
    for (int i = 0; i < 4; i++) {
        int k = lane + 32 * i;
        if (k < K) {
            int t = lmin * lmin + k;          // global sph index
            int l = lmin;
            while ((l + 1) * (l + 1) <= t) l++;
            int m = t - l * l - l;
            int a = (m < 0) ? -m : m;
            int src = iclamp(b * NIDX + l * (LMAX + 1) + a, coeff_elems - 1);
            float re = cre[src], im = cim[src];
            if (m < 0) { float s = (a & 1) ? -1.f : 1.f; re *= s; im *= -s; }
            // Re[(ax + i*ay) * (re - i*im)] = ax*re + ay*im
            sh_p[warp][k] = ax[i] * re + ay[i] * im;
        }
    }
    __syncwarp();

    // Segmented reduce: lane li sums block l = lmin + li, writes output col.
    if (lane < nl) {
        int l  = lmin + lane;
        int s  = l * l - lmin * lmin;
        int wd = 2 * l + 1;
        float sx = 0.f;
        for (int q = 0; q < wd; q++) sx += sh_p[warp][s + q];
        int of = b * NCOLS + col_base + lane;
        if (of >= 0 && of < out_elems) outf[of] = sx;   // <= out_size-1: safe
    }
}

// ---------------------------------------------------------------------------
extern "C" void kernel_launch(void* const* d_in, const int* in_sizes, int n_in,
                              void* d_out, int out_size) {
    const float* cre = (const float*)d_in[0];
    const float* cim = (const float*)d_in[1];
    const float* cg  = (const float*)d_in[2];

    int coeff_elems = in_sizes[0];            // 1982464
    int cg_elems    = in_sizes[2];            // 1824130
    int B           = coeff_elems / NIDX;     // 16384

    dim3 grid((B + NW - 1) / NW, NPAIRS);
    so3_kernel<<<grid, NW * 32>>>(cre, cim, cg, (float*)d_out,
                                  B, coeff_elems, cg_elems, out_size);
}

// round 13
// speedup vs baseline: 3.2664x; 3.2664x over previous
#include <cuda_runtime.h>

#define LMAX   10
#define NIDX   121
#define NCOLS  381
#define NPAIRS 66
#define KPAD   128                 // padded columns per cg row (floats)
#define KP4    (KPAD / 4)          // per row in float4
#define SUMD   8206
#define TB     32                  // batch rows per CTA
#define JC     64                  // j-chunk staged in smem
#define NB     16384
#define NF     (NB * NIDX)
#define NCGP   (SUMD * KPAD)

struct PairInfo {
    int l1, l2, d, K;
    int cg_off, cgp4_off, f3_off, col_base, nl;
};
struct PairTable { PairInfo p[NPAIRS]; };

// Static device scratch (allocation-free). float4 => 16B-aligned base.
__device__ float2 g_F[NF];              // expanded coefficients, 15.9 MB
__device__ float4 g_cgp4[NCGP / 4];     // packed cg, 4.2 MB

__device__ __forceinline__ int iclamp(int x, int hi) { return x < hi ? x : hi; }

// ---------------------------------------------------------------------------
// Kernel 1: F[b, l^2 + j], m = j-l.  m>=0: c[b,l,m]; m<0: (-1)^|m| conj.
// ---------------------------------------------------------------------------
__global__ void expand_kernel(const float* __restrict__ cre,
                              const float* __restrict__ cim,
                              int B, int coeff_elems) {
    int i = blockIdx.x * blockDim.x + threadIdx.x;
    if (i >= B * NIDX || i >= NF) return;
    int b = i / NIDX, t = i - b * NIDX;
    int l = 0;
    while ((l + 1) * (l + 1) <= t) l++;
    int m = t - l * l - l;
    int a = (m < 0) ? -m : m;
    int src = iclamp(b * NIDX + l * (LMAX + 1) + a, coeff_elems - 1);
    float re = cre[src], im = cim[src];
    if (m < 0) { float s = (a & 1) ? -1.f : 1.f; re *= s; im *= -s; }
    g_F[i] = make_float2(re, im);
}

// ---------------------------------------------------------------------------
// Kernel 2: pack cg rows -> KPAD-wide; cols [0,K) kept, rest zero.
// ---------------------------------------------------------------------------
__global__ void pack_kernel(const float* __restrict__ cg, PairTable T,
                            int cg_elems) {
    float* gcgp = (float*)g_cgp4;
    PairInfo pi = T.p[blockIdx.y];
    int n = pi.d * KPAD;
    int base = pi.cgp4_off * 4;
    for (int i = blockIdx.x * blockDim.x + threadIdx.x; i < n;
         i += gridDim.x * blockDim.x) {
        int j = i >> 7;
        int k = i & (KPAD - 1);
        float v = 0.0f;
        if (k < pi.K) v = cg[iclamp(pi.cg_off + j * pi.d + k, cg_elems - 1)];
        int dst = base + i;
        if (dst < NCGP) gcgp[dst] = v;
    }
}

// ---------------------------------------------------------------------------
// Kernel 3: fused tp -> (tp @ cg) -> Re( . * conj(F3) ) -> seg-reduce -> out.
// CTA = (pair, 32 batch rows). Warp w owns rows {2w, 2w+1};
// lane owns columns k = 4*lane + i (one LDG.128 per j).
// ---------------------------------------------------------------------------
__global__ void __launch_bounds__(512)
main_kernel(float* __restrict__ outf, PairTable T, int B, int out_elems) {
    __shared__ float2 f12_s[TB][45];     // f1 | f2 per row (padded stride)
    __shared__ float2 tp_s[JC][TB];      // staged tensor products
    __shared__ float  pr_s[TB][KPAD];    // epilogue real products

    const PairInfo pi = T.p[blockIdx.y];
    const int d1 = 2 * pi.l1 + 1, d2 = 2 * pi.l2 + 1;
    const int width = d1 + d2;
    const int b_base = blockIdx.x * TB;
    const int tid  = threadIdx.x;
    const int lane = tid & 31;
    const int w    = tid >> 5;

    // Stage f1 | f2 for the 32 batch rows of this CTA
    for (int t = tid; t < TB * width; t += 512) {
        int b = t / width, idx = t - b * width;
        int src = (idx < d1) ? (pi.l1 * pi.l1 + idx)
                             : (pi.l2 * pi.l2 + (idx - d1));
        f12_s[b][idx] = g_F[(b_base + b) * NIDX + src];
    }
    __syncthreads();

    const int b0 = 2 * w, b1 = b0 + 1;
    float a0x[4], a0y[4], a1x[4], a1y[4];
#pragma unroll
    for (int i = 0; i < 4; i++) { a0x[i]=0.f; a0y[i]=0.f; a1x[i]=0.f; a1y[i]=0.f; }

    const float4* cgp = g_cgp4 + pi.cgp4_off + lane;

    for (int jc = 0; jc < pi.d; jc += JC) {
        int jcount = min(JC, pi.d - jc);
        // Cooperative tp stage: tp_s[jj][b] = f1[b][j1] * f2[b][j2]
        for (int t = tid; t < TB * jcount; t += 512) {
            int jj = t >> 5;
            int b  = t & 31;
            int j  = jc + jj;
            int j1 = j / d2;
            int j2 = j - j1 * d2;
            float2 x = f12_s[b][j1];
            float2 y = f12_s[b][d1 + j2];
            tp_s[jj][b] =
                make_float2(x.x * y.x - x.y * y.y, x.x * y.y + x.y * y.x);
        }
        __syncthreads();

        const float4* crow = cgp + (size_t)jc * KP4;
#pragma unroll 4
        for (int jj = 0; jj < jcount; jj++) {
            float4 c  = crow[jj * KP4];          // 4 consecutive cg columns
            float2 t0 = tp_s[jj][b0];            // broadcast
            float2 t1 = tp_s[jj][b1];
            a0x[0] += t0.x * c.x; a0y[0] += t0.y * c.x;
            a0x[1] += t0.x * c.y; a0y[1] += t0.y * c.y;
            a0x[2] += t0.x * c.z; a0y[2] += t0.y * c.z;
            a0x[3] += t0.x * c.w; a0y[3] += t0.y * c.w;
            a1x[0] += t1.x * c.x; a1y[0] += t1.y * c.x;
            a1x[1] += t1.x * c.y; a1y[1] += t1.y * c.y;
            a1x[2] += t1.x * c.z; a1y[2] += t1.y * c.z;
            a1x[3] += t1.x * c.w; a1y[3] += t1.y * c.w;
        }
        __syncthreads();
    }

    // Epilogue: Re( transformed_k * conj(F3_k) )
#pragma unroll
    for (int i = 0; i < 4; i++) {
        int k = 4 * lane + i;
        if (k < pi.K) {
            float2 fA = g_F[(b_base + b0) * NIDX + pi.f3_off + k];
            float2 fB = g_F[(b_base + b1) * NIDX + pi.f3_off + k];
            pr_s[b0][k] = a0x[i] * fA.x + a0y[i] * fA.y;
            pr_s[b1][k] = a1x[i] * fB.x + a1y[i] * fB.y;
        }
    }
    __syncthreads();

    // Segmented reduce per (batch row, output l); only k < K is ever read.
    const int lmin = pi.l2 - pi.l1;
    for (int t = tid; t < TB * pi.nl; t += 512) {
        int b  = t / pi.nl;
        int li = t - b * pi.nl;
        int l  = lmin + li;
        int s  = l * l - lmin * lmin;
        int wd = 2 * l + 1;
        float sx = 0.f;
        for (int q = 0; q < wd; q++) sx += pr_s[b][s + q];
        int of = (b_base + b) * NCOLS + pi.col_base + li;
        if (of >= 0 && of < out_elems) outf[of] = sx;
    }
}

// ---------------------------------------------------------------------------
extern "C" void kernel_launch(void* const* d_in, const int* in_sizes, int n_in,
                              void* d_out, int out_size) {
    const float* cre = (const float*)d_in[0];
    const float* cim = (const float*)d_in[1];
    const float* cg  = (const float*)d_in[2];

    int coeff_elems = in_sizes[0];           // 1982464
    int cg_elems    = in_sizes[2];           // 1824130
    int B           = coeff_elems / NIDX;    // 16384

    PairTable T;
    int off = 0, col = 0, cgp4off = 0, idx = 0;
    for (int l1 = 0; l1 <= LMAX; l1++) {
        for (int l2 = l1; l2 <= LMAX; l2++) {
            int d1 = 2 * l1 + 1, d2 = 2 * l2 + 1, d = d1 * d2;
            int lmin = l2 - l1;
            int lmax = (l1 + l2 < LMAX) ? (l1 + l2) : LMAX;
            int K = (lmax + 1) * (lmax + 1) - lmin * lmin;
            PairInfo pi;
            pi.l1 = l1; pi.l2 = l2; pi.d = d; pi.K = K;
            pi.cg_off = off; pi.cgp4_off = cgp4off;
            pi.f3_off = lmin * lmin;
            pi.col_base = col; pi.nl = lmax - lmin + 1;
            T.p[idx++] = pi;
            off     += d * d;
            col     += lmax - lmin + 1;
            cgp4off += d * KP4;
        }
    }
    // Heavy pairs first (tail balance)
    for (int i = 1; i < NPAIRS; i++) {
        PairInfo key = T.p[i];
        int j = i - 1;
        while (j >= 0 && T.p[j].d < key.d) { T.p[j + 1] = T.p[j]; j--; }
        T.p[j + 1] = key;
    }

    expand_kernel<<<(B * NIDX + 255) / 256, 256>>>(cre, cim, B, coeff_elems);
    pack_kernel<<<dim3(64, NPAIRS), 256>>>(cg, T, cg_elems);
    main_kernel<<<dim3(B / TB, NPAIRS), 512>>>((float*)d_out, T, B, out_size);
}

// round 16
// speedup vs baseline: 5.3313x; 1.6322x over previous
#include <cuda_runtime.h>

#define LMAX   10
#define NIDX   121
#define NCOLS  381
#define NPAIRS 66
#define KPAD   128
#define KP4    (KPAD / 4)
#define TB     32                 // batch rows per CTA
#define JC     32                 // scheduled-j chunk staged in smem
#define NB     16384
#define NF     (NB * NIDX)
#define SUMNS  4796               // sum over pairs of ns = (d+1)/2 + l1 + l2

struct PairInfo {
    int l1, l2, d, d2, K, ns;
    int cg_off, cgs4_off, f3_off, col_base, nl;
};
struct PairTable { PairInfo p[NPAIRS]; };

// Static device scratch (allocation-free). float4 => 16B-aligned.
__device__ float2 g_F[NF];                // expanded coefficients, 15.9 MB
__device__ float4 g_cgP4[SUMNS * KP4];    // folded cg "+", 2.46 MB
__device__ float4 g_cgM4[SUMNS * KP4];    // folded cg "-", 2.46 MB

__device__ __forceinline__ int iclamp(int x, int hi) { return x < hi ? x : hi; }

// Closed-form schedule: slot t of a pair -> original j index.
// t < (d+1)/2           : j = t            (off-axis => folded with d-1-j)
// t >= (d+1)/2          : upper-half axis singles
__device__ __forceinline__ int sched_j(int t, int d, int d2, int l1, int l2) {
    int half = (d + 1) >> 1;
    if (t < half) return t;
    int u = t - half;
    return (u < l1) ? (l1 + 1 + u) * d2 + l2
                    : l1 * d2 + l2 + 1 + (u - l1);
}

// ---------------------------------------------------------------------------
// Kernel 1: F[b, l^2 + j], m = j-l.  m>=0: c[b,l,m]; m<0: (-1)^|m| conj.
// ---------------------------------------------------------------------------
__global__ void expand_kernel(const float* __restrict__ cre,
                              const float* __restrict__ cim,
                              int B, int coeff_elems) {
    int i = blockIdx.x * blockDim.x + threadIdx.x;
    if (i >= B * NIDX || i >= NF) return;
    int b = i / NIDX, t = i - b * NIDX;
    int l = 0;
    while ((l + 1) * (l + 1) <= t) l++;
    int m = t - l * l - l;
    int a = (m < 0) ? -m : m;
    int src = iclamp(b * NIDX + l * (LMAX + 1) + a, coeff_elems - 1);
    float re = cre[src], im = cim[src];
    if (m < 0) { float s = (a & 1) ? -1.f : 1.f; re *= s; im *= -s; }
    g_F[i] = make_float2(re, im);
}

// ---------------------------------------------------------------------------
// Kernel 2: build folded cgP/cgM, KPAD-wide, cols [0,K) kept, rest zero.
//   folded (off-axis): cgP = cg[j] + s*cg[d-1-j],  cgM = cg[j] - s*cg[d-1-j]
//   single (axis)    : cgP = cgM = cg[j]
// ---------------------------------------------------------------------------
__global__ void pack_kernel(const float* __restrict__ cg, PairTable T,
                            int cg_elems) {
    float* gP = (float*)g_cgP4;
    float* gM = (float*)g_cgM4;
    PairInfo pi = T.p[blockIdx.y];
    int n = pi.ns * KPAD;
    int base = pi.cgs4_off * 4;
    for (int i = blockIdx.x * blockDim.x + threadIdx.x; i < n;
         i += gridDim.x * blockDim.x) {
        int jj = i >> 7;
        int k  = i & (KPAD - 1);
        int j  = sched_j(jj, pi.d, pi.d2, pi.l1, pi.l2);
        int j1 = j / pi.d2;
        int j2 = j - j1 * pi.d2;
        float vP = 0.f, vM = 0.f;
        if (k < pi.K) {
            float a = cg[iclamp(pi.cg_off + j * pi.d + k, cg_elems - 1)];
            bool folded = (j1 != pi.l1) && (j2 != pi.l2);
            if (folded) {
                float b = cg[iclamp(pi.cg_off + (pi.d - 1 - j) * pi.d + k,
                                    cg_elems - 1)];
                float s = ((j1 - pi.l1 + j2 - pi.l2) & 1) ? -1.f : 1.f;
                vP = a + s * b;
                vM = a - s * b;
            } else {
                vP = a;
                vM = a;
            }
        }
        gP[base + i] = vP;
        gM[base + i] = vM;
    }
}

// ---------------------------------------------------------------------------
// Kernel 3: folded tp-GEMM + epilogue + segmented reduce.
// CTA = (pair, 32 batch rows), 256 threads / 8 warps.
// Warp w owns rows 4w..4w+3; lane owns columns k = 4*lane + i.
// Inner step: 2 LDG.128 (cgP,cgM) + 2 LDS.128 (tp of 4 rows) + 32 FFMA.
// ---------------------------------------------------------------------------
__global__ void __launch_bounds__(256, 4)
main_kernel(float* __restrict__ outf, PairTable T, int out_elems) {
    __shared__ float2 f12_s[TB][45];          // f1 | f2 per batch row
    __shared__ unsigned char j1t[256], j2t[256];
    __shared__ float un_s[TB * KPAD];         // 16KB: tp stage / epilogue union
    float2* tp2 = (float2*)un_s;              // tp2[jj*TB + b]
    float4* tp4 = (float4*)un_s;              // tp4[jj*16 + b/2]

    const PairInfo pi = T.p[blockIdx.y];
    const int d1 = 2 * pi.l1 + 1;
    const int d2 = pi.d2;
    const int width = d1 + d2;
    const int b_base = blockIdx.x * TB;
    const int tid  = threadIdx.x;
    const int lane = tid & 31;
    const int w    = tid >> 5;

    // Stage f1 | f2 for the 32 batch rows
    for (int t = tid; t < TB * width; t += 256) {
        int b = t / width, idx = t - b * width;
        int src = (idx < d1) ? (pi.l1 * pi.l1 + idx)
                             : (pi.l2 * pi.l2 + (idx - d1));
        f12_s[b][idx] = g_F[(b_base + b) * NIDX + src];
    }
    // Schedule tables (ns <= 241)
    for (int t = tid; t < pi.ns; t += 256) {
        int j  = sched_j(t, pi.d, d2, pi.l1, pi.l2);
        int j1 = j / d2;
        j1t[t] = (unsigned char)j1;
        j2t[t] = (unsigned char)(j - j1 * d2);
    }
    __syncthreads();

    float ax[4][4], ay[4][4];
#pragma unroll
    for (int r = 0; r < 4; r++)
#pragma unroll
        for (int i = 0; i < 4; i++) { ax[r][i] = 0.f; ay[r][i] = 0.f; }

    const float4* rp0 = g_cgP4 + pi.cgs4_off + lane;
    const float4* rm0 = g_cgM4 + pi.cgs4_off + lane;

    for (int jc0 = 0; jc0 < pi.ns; jc0 += JC) {
        int jcount = min(JC, pi.ns - jc0);
        // Cooperative tp stage for scheduled slots [jc0, jc0+jcount)
        for (int t = tid; t < (jcount << 5); t += 256) {
            int jj = t >> 5;
            int b  = t & 31;
            int jg = jc0 + jj;
            float2 x = f12_s[b][j1t[jg]];
            float2 y = f12_s[b][d1 + j2t[jg]];
            tp2[jj * TB + b] =
                make_float2(x.x * y.x - x.y * y.y, x.x * y.y + x.y * y.x);
        }
        __syncthreads();

        const float4* rp = rp0 + (size_t)jc0 * KP4;
        const float4* rm = rm0 + (size_t)jc0 * KP4;
#pragma unroll 2
        for (int jj = 0; jj < jcount; jj++) {
            float4 cp = rp[jj * KP4];
            float4 cm = rm[jj * KP4];
            float4 tA = tp4[jj * 16 + 2 * w];       // rows 4w, 4w+1
            float4 tB = tp4[jj * 16 + 2 * w + 1];   // rows 4w+2, 4w+3
            ax[0][0] += tA.x * cp.x; ax[0][1] += tA.x * cp.y;
            ax[0][2] += tA.x * cp.z; ax[0][3] += tA.x * cp.w;
            ay[0][0] += tA.y * cm.x; ay[0][1] += tA.y * cm.y;
            ay[0][2] += tA.y * cm.z; ay[0][3] += tA.y * cm.w;
            ax[1][0] += tA.z * cp.x; ax[1][1] += tA.z * cp.y;
            ax[1][2] += tA.z * cp.z; ax[1][3] += tA.z * cp.w;
            ay[1][0] += tA.w * cm.x; ay[1][1] += tA.w * cm.y;
            ay[1][2] += tA.w * cm.z; ay[1][3] += tA.w * cm.w;
            ax[2][0] += tB.x * cp.x; ax[2][1] += tB.x * cp.y;
            ax[2][2] += tB.x * cp.z; ax[2][3] += tB.x * cp.w;
            ay[2][0] += tB.y * cm.x; ay[2][1] += tB.y * cm.y;
            ay[2][2] += tB.y * cm.z; ay[2][3] += tB.y * cm.w;
            ax[3][0] += tB.z * cp.x; ax[3][1] += tB.z * cp.y;
            ax[3][2] += tB.z * cp.z; ax[3][3] += tB.z * cp.w;
            ay[3][0] += tB.w * cm.x; ay[3][1] += tB.w * cm.y;
            ay[3][2] += tB.w * cm.z; ay[3][3] += tB.w * cm.w;
        }
        __syncthreads();
    }

    // Epilogue: Re( transformed_k * conj(F3_k) ) into un_s (pr[b][k])
#pragma unroll
    for (int r = 0; r < 4; r++) {
        int b = 4 * w + r;
        int gbase = (b_base + b) * NIDX + pi.f3_off;
#pragma unroll
        for (int i = 0; i < 4; i++) {
            int k = 4 * lane + i;
            if (k < pi.K) {
                float2 f = g_F[gbase + k];
                un_s[b * KPAD + k] = ax[r][i] * f.x + ay[r][i] * f.y;
            }
        }
    }
    __syncthreads();

    // Segmented reduce per (batch row, output l); reads only k < K.
    const int lmin = pi.l2 - pi.l1;
    for (int t = tid; t < TB * pi.nl; t += 256) {
        int b  = t / pi.nl;
        int li = t - b * pi.nl;
        int l  = lmin + li;
        int s  = l * l - lmin * lmin;
        int wd = 2 * l + 1;
        float sx = 0.f;
        for (int q = 0; q < wd; q++) sx += un_s[b * KPAD + s + q];
        int of = (b_base + b) * NCOLS + pi.col_base + li;
        if (of >= 0 && of < out_elems) outf[of] = sx;
    }
}

// ---------------------------------------------------------------------------
extern "C" void kernel_launch(void* const* d_in, const int* in_sizes, int n_in,
                              void* d_out, int out_size) {
    const float* cre = (const float*)d_in[0];
    const float* cim = (const float*)d_in[1];
    const float* cg  = (const float*)d_in[2];

    int coeff_elems = in_sizes[0];           // 1982464
    int cg_elems    = in_sizes[2];           // 1824130
    int B           = coeff_elems / NIDX;    // 16384

    PairTable T;
    int off = 0, col = 0, cgs4off = 0, idx = 0;
    for (int l1 = 0; l1 <= LMAX; l1++) {
        for (int l2 = l1; l2 <= LMAX; l2++) {
            int d1 = 2 * l1 + 1, d2 = 2 * l2 + 1, d = d1 * d2;
            int lmin = l2 - l1;
            int lmax = (l1 + l2 < LMAX) ? (l1 + l2) : LMAX;
            int K  = (lmax + 1) * (lmax + 1) - lmin * lmin;
            int ns = (d + 1) / 2 + l1 + l2;
            PairInfo pi;
            pi.l1 = l1; pi.l2 = l2; pi.d = d; pi.d2 = d2;
            pi.K = K; pi.ns = ns;
            pi.cg_off = off; pi.cgs4_off = cgs4off;
            pi.f3_off = lmin * lmin;
            pi.col_base = col; pi.nl = lmax - lmin + 1;
            T.p[idx++] = pi;
            off     += d * d;
            col     += lmax - lmin + 1;
            cgs4off += ns * KP4;
        }
    }
    // Heavy pairs first (tail balance)
    for (int i = 1; i < NPAIRS; i++) {
        PairInfo key = T.p[i];
        int j = i - 1;
        while (j >= 0 && T.p[j].ns < key.ns) { T.p[j + 1] = T.p[j]; j--; }
        T.p[j + 1] = key;
    }

    expand_kernel<<<(B * NIDX + 255) / 256, 256>>>(cre, cim, B, coeff_elems);
    pack_kernel<<<dim3(32, NPAIRS), 256>>>(cg, T, cg_elems);
    main_kernel<<<dim3(B / TB, NPAIRS), 256>>>((float*)d_out, T, out_size);
}